// round 1
// baseline (speedup 1.0000x reference)
#include <cuda_runtime.h>
#include <cstdint>

#define DIMV   512
#define NTOK   256
#define NKEEP  128
#define HID    102
#define HP     104
#define KP     51
#define WP     52
#define OUTROWS 52

typedef unsigned long long ull;

struct __align__(16) Smem {
    float A[128 * 72];      // A tile (LN-applied sel rows), also phase-1 scratch
    float Bt[64 * 104];     // W1 tile
    float H[128 * 104];     // gelu(h@W1+b1)
    float W2s[102 * 52];    // W2 padded
    float w[128 * 52];      // softmaxed weights [token][p], col 51 = 0
    float colsum[512];      // -> glo (in place)
    float g[512];
    float bln[512];
    float rowsum[256];
    float rowsumsq[256];
    float score[256];
    float nscore[128];
    float nw[128];
    float mu[128];
    float rinv[128];
    float b1p[104];
    float b2s[52];
    int   selidx[128];
    int   nonidx[128];
    float red[16];
    float ssq;
};

__device__ __forceinline__ ull ffma2(ull a, ull b, ull c) {
    ull d;
    asm("fma.rn.f32x2 %0, %1, %2, %3;" : "=l"(d) : "l"(a), "l"(b), "l"(c));
    return d;
}
__device__ __forceinline__ ull pack2(float x, float y) {
    ull d;
    asm("mov.b64 %0, {%1, %2};" : "=l"(d) : "f"(x), "f"(y));
    return d;
}
__device__ __forceinline__ float2 unpack2(ull v) {
    float2 r;
    asm("mov.b64 {%0, %1}, %2;" : "=f"(r.x), "=f"(r.y) : "l"(v));
    return r;
}
__device__ __forceinline__ float gelu_exact(float v) {
    return 0.5f * v * (1.0f + erff(v * 0.70710678118654752f));
}

__global__ __launch_bounds__(512, 1)
void ATRM_73581379715509_kernel(
    const float* __restrict__ x, const float* __restrict__ ca,
    const float* __restrict__ lng, const float* __restrict__ lnb,
    const float* __restrict__ W1, const float* __restrict__ b1,
    const float* __restrict__ W2, const float* __restrict__ b2,
    const float* __restrict__ scale, float* __restrict__ out)
{
    extern __shared__ char smem_raw[];
    Smem& s = *reinterpret_cast<Smem*>(smem_raw);

    const int b    = blockIdx.x;
    const int tid  = threadIdx.x;
    const int warp = tid >> 5;
    const int lane = tid & 31;
    const float* __restrict__ xb = x + (size_t)b * NTOK * DIMV;
    float* __restrict__ ob = out + (size_t)b * OUTROWS * DIMV;

    // ---- constant loads + pads ----
    s.g[tid]   = lng[tid];
    s.bln[tid] = lnb[tid];
    if (tid < HP) s.b1p[tid] = (tid < HID) ? b1[tid] : 0.0f;
    if (tid < KP) s.b2s[tid] = b2[tid];
    if (tid < 128) s.Bt[(tid >> 1) * 104 + 102 + (tid & 1)] = 0.0f;  // B pad cols
    if (tid < HID) s.W2s[tid * 52 + 51] = 0.0f;                      // W2 pad col

    // ---- PHASE 1: rowsum/rowsumsq + per-warp column partials ----
    float4 cs0 = make_float4(0,0,0,0), cs1 = cs0, cs2 = cs0, cs3 = cs0;
    #pragma unroll 1
    for (int r = 0; r < 16; r++) {
        const int t = warp * 16 + r;
        const float4* row = reinterpret_cast<const float4*>(xb + t * DIMV);
        float4 v0 = row[lane], v1 = row[lane + 32], v2 = row[lane + 64], v3 = row[lane + 96];
        float rs = v0.x+v0.y+v0.z+v0.w + v1.x+v1.y+v1.z+v1.w
                 + v2.x+v2.y+v2.z+v2.w + v3.x+v3.y+v3.z+v3.w;
        float rq = v0.x*v0.x+v0.y*v0.y+v0.z*v0.z+v0.w*v0.w
                 + v1.x*v1.x+v1.y*v1.y+v1.z*v1.z+v1.w*v1.w
                 + v2.x*v2.x+v2.y*v2.y+v2.z*v2.z+v2.w*v2.w
                 + v3.x*v3.x+v3.y*v3.y+v3.z*v3.z+v3.w*v3.w;
        cs0.x += v0.x; cs0.y += v0.y; cs0.z += v0.z; cs0.w += v0.w;
        cs1.x += v1.x; cs1.y += v1.y; cs1.z += v1.z; cs1.w += v1.w;
        cs2.x += v2.x; cs2.y += v2.y; cs2.z += v2.z; cs2.w += v2.w;
        cs3.x += v3.x; cs3.y += v3.y; cs3.z += v3.z; cs3.w += v3.w;
        #pragma unroll
        for (int off = 16; off; off >>= 1) {
            rs += __shfl_down_sync(0xffffffffu, rs, off);
            rq += __shfl_down_sync(0xffffffffu, rq, off);
        }
        if (lane == 0) { s.rowsum[t] = rs; s.rowsumsq[t] = rq; }
    }
    {
        float4* cp = reinterpret_cast<float4*>(s.A + warp * 512);
        cp[lane] = cs0; cp[lane + 32] = cs1; cp[lane + 64] = cs2; cp[lane + 96] = cs3;
    }
    __syncthreads();

    // deterministic column reduction (no atomics)
    float cacc = 0.0f;
    #pragma unroll
    for (int w0 = 0; w0 < 16; w0++) cacc += s.A[w0 * 512 + tid];
    {
        float p = cacc * cacc;
        #pragma unroll
        for (int off = 16; off; off >>= 1) p += __shfl_down_sync(0xffffffffu, p, off);
        if (lane == 0) s.red[warp] = p;
    }
    __syncthreads();
    if (tid == 0) {
        float t = 0.0f;
        #pragma unroll
        for (int i = 0; i < 16; i++) t += s.red[i];
        s.ssq = t;
    }
    __syncthreads();
    {
        // glo = colsum / max(||colsum||, 256*1e-12)
        const float inv = 1.0f / fmaxf(sqrtf(s.ssq), 2.56e-10f);
        s.colsum[tid] = cacc * inv;
    }
    __syncthreads();

    // ---- PHASE 2: scores ----
    {
        const float4* glo4 = reinterpret_cast<const float4*>(s.colsum);
        #pragma unroll 1
        for (int r = 0; r < 16; r++) {
            const int t = warp * 16 + r;
            const float4* row = reinterpret_cast<const float4*>(xb + t * DIMV);
            float d = 0.0f;
            #pragma unroll
            for (int q = 0; q < 4; q++) {
                float4 v = row[lane + 32 * q];
                float4 gg = glo4[lane + 32 * q];
                d += v.x * gg.x + v.y * gg.y + v.z * gg.z + v.w * gg.w;
            }
            #pragma unroll
            for (int off = 16; off; off >>= 1) d += __shfl_down_sync(0xffffffffu, d, off);
            if (lane == 0) {
                float nr = sqrtf(s.rowsumsq[t]);
                s.score[t] = d / fmaxf(nr, 1e-12f) + ca[(size_t)b * NTOK + t];
            }
        }
    }
    __syncthreads();

    // ---- PHASE 3: rank-based partition (deterministic, matches stable argsort) ----
    if (tid < NTOK) {
        const float sc = s.score[tid];
        int rank = 0;
        #pragma unroll 4
        for (int j = 0; j < NTOK; j++) {
            float sj = s.score[j];
            rank += (sj > sc) || (sj == sc && j < tid);
        }
        const float mu  = s.rowsum[tid] * (1.0f / 512.0f);
        const float var = s.rowsumsq[tid] * (1.0f / 512.0f) - mu * mu;
        if (rank < NKEEP) {
            s.selidx[rank] = tid;
            s.mu[rank]     = mu;
            s.rinv[rank]   = rsqrtf(var + 1e-5f);
        } else {
            s.nonidx[rank - NKEEP] = tid;
            s.nscore[rank - NKEEP] = sc;
        }
    }
    __syncthreads();

    // ---- PHASE 4: softmax over non-kept scores (warp 0) ----
    if (warp == 0) {
        float v0 = s.nscore[lane], v1 = s.nscore[lane + 32],
              v2 = s.nscore[lane + 64], v3 = s.nscore[lane + 96];
        float m = fmaxf(fmaxf(v0, v1), fmaxf(v2, v3));
        #pragma unroll
        for (int off = 16; off; off >>= 1) m = fmaxf(m, __shfl_xor_sync(0xffffffffu, m, off));
        float e0 = expf(v0 - m), e1 = expf(v1 - m), e2 = expf(v2 - m), e3 = expf(v3 - m);
        float su = e0 + e1 + e2 + e3;
        #pragma unroll
        for (int off = 16; off; off >>= 1) su += __shfl_xor_sync(0xffffffffu, su, off);
        const float inv = 1.0f / su;
        s.nw[lane] = e0 * inv; s.nw[lane + 32] = e1 * inv;
        s.nw[lane + 64] = e2 * inv; s.nw[lane + 96] = e3 * inv;
    }
    __syncthreads();

    // ---- PHASE 5: extra row (out row 51) ----
    {
        float acc = 0.0f;
        #pragma unroll 4
        for (int k = 0; k < 128; k++)
            acc += s.nw[k] * xb[(size_t)s.nonidx[k] * DIMV + tid];
        ob[51 * DIMV + tid] = acc;
    }

    // ---- GEMM1: H = gelu( LN(sel) @ W1 + b1 ), split-K f32x2 ----
    const bool act = (tid < 416);
    const int  kg  = tid / 208;          // K-group 0/1
    const int  rr  = tid % 208;
    const int  mt  = rr / 13, nt = rr % 13;
    const int  m0  = mt * 8,  n0 = nt * 8;

    ull acc[8][4];
    #pragma unroll
    for (int i = 0; i < 8; i++)
        #pragma unroll
        for (int j = 0; j < 4; j++) acc[i][j] = 0ull;

    #pragma unroll 1
    for (int kt = 0; kt < 8; kt++) {
        const int d0 = kt * 64;
        // fill A (LN applied), layout [t][72]
        #pragma unroll
        for (int j = tid; j < 2048; j += 512) {
            const int t  = j >> 4;
            const int dv = (j & 15) << 2;
            const int rowi = s.selidx[t];
            float4 v = *reinterpret_cast<const float4*>(xb + (size_t)rowi * DIMV + d0 + dv);
            const float muv = s.mu[t], ri = s.rinv[t];
            const int dd = d0 + dv;
            float4 y;
            y.x = (v.x - muv) * ri * s.g[dd + 0] + s.bln[dd + 0];
            y.y = (v.y - muv) * ri * s.g[dd + 1] + s.bln[dd + 1];
            y.z = (v.z - muv) * ri * s.g[dd + 2] + s.bln[dd + 2];
            y.w = (v.w - muv) * ri * s.g[dd + 3] + s.bln[dd + 3];
            *reinterpret_cast<float4*>(&s.A[t * 72 + dv]) = y;
        }
        // fill B = W1 tile, layout [dk][104] (cols 102/103 pre-zeroed)
        #pragma unroll
        for (int j = tid; j < 64 * HID; j += 512) {
            const int dk = j / HID;
            const int c  = j - dk * HID;
            s.Bt[dk * 104 + c] = W1[(size_t)(d0 + dk) * HID + c];
        }
        __syncthreads();
        if (act) {
            const float* Abase = s.A + m0 * 72 + kg * 32;
            const float* Bbase = s.Bt + (size_t)(kg * 32) * 104 + n0;
            #pragma unroll 2
            for (int dk = 0; dk < 32; dk++) {
                ull a2[8];
                #pragma unroll
                for (int i = 0; i < 8; i++) {
                    float av = Abase[i * 72 + dk];
                    a2[i] = pack2(av, av);
                }
                const ull* bp = reinterpret_cast<const ull*>(Bbase + (size_t)dk * 104);
                ull b2v[4];
                #pragma unroll
                for (int j = 0; j < 4; j++) b2v[j] = bp[j];
                #pragma unroll
                for (int i = 0; i < 8; i++)
                    #pragma unroll
                    for (int j = 0; j < 4; j++)
                        acc[i][j] = ffma2(a2[i], b2v[j], acc[i][j]);
            }
        }
        __syncthreads();
    }
    // combine split-K + bias + gelu
    if (act && kg == 0) {
        #pragma unroll
        for (int i = 0; i < 8; i++) {
            ull* hp = reinterpret_cast<ull*>(&s.H[(m0 + i) * 104 + n0]);
            #pragma unroll
            for (int j = 0; j < 4; j++) hp[j] = acc[i][j];
        }
    }
    __syncthreads();
    if (act && kg == 1) {
        #pragma unroll
        for (int i = 0; i < 8; i++) {
            float* hrow = &s.H[(m0 + i) * 104];
            #pragma unroll
            for (int j = 0; j < 4; j++) {
                float2 p = unpack2(acc[i][j]);
                const int n = n0 + 2 * j;
                float v0 = p.x + hrow[n]     + s.b1p[n];
                float v1 = p.y + hrow[n + 1] + s.b1p[n + 1];
                hrow[n]     = gelu_exact(v0);
                hrow[n + 1] = gelu_exact(v1);
            }
        }
    }
    __syncthreads();

    // ---- GEMM2: w_pre = H @ W2 + b2, times scale ----
    #pragma unroll
    for (int j = tid; j < HID * KP; j += 512)
        s.W2s[(j / KP) * 52 + (j % KP)] = W2[j];
    __syncthreads();
    {
        const int t = tid >> 2, q = tid & 3;
        float a2[13];
        #pragma unroll
        for (int i = 0; i < 13; i++) a2[i] = 0.0f;
        const float* hrow = &s.H[t * 104];
        #pragma unroll 2
        for (int k = 0; k < HID; k++) {
            const float h = hrow[k];
            const float* wrow = &s.W2s[k * 52 + q];
            #pragma unroll
            for (int i = 0; i < 13; i++) a2[i] += h * wrow[4 * i];
        }
        const float sv = scale[0];
        #pragma unroll
        for (int i = 0; i < 13; i++) {
            const int c = q + 4 * i;
            if (c < KP) s.w[t * 52 + c] = (a2[i] + s.b2s[c]) * sv;
        }
    }
    __syncthreads();

    // ---- softmax over 128 tokens per output column ----
    for (int c = warp; c < KP; c += 16) {
        float v0 = s.w[(lane) * 52 + c], v1 = s.w[(lane + 32) * 52 + c],
              v2 = s.w[(lane + 64) * 52 + c], v3 = s.w[(lane + 96) * 52 + c];
        float m = fmaxf(fmaxf(v0, v1), fmaxf(v2, v3));
        #pragma unroll
        for (int off = 16; off; off >>= 1) m = fmaxf(m, __shfl_xor_sync(0xffffffffu, m, off));
        float e0 = expf(v0 - m), e1 = expf(v1 - m), e2 = expf(v2 - m), e3 = expf(v3 - m);
        float su = e0 + e1 + e2 + e3;
        #pragma unroll
        for (int off = 16; off; off >>= 1) su += __shfl_xor_sync(0xffffffffu, su, off);
        const float inv = 1.0f / su;
        s.w[(lane) * 52 + c] = e0 * inv;
        s.w[(lane + 32) * 52 + c] = e1 * inv;
        s.w[(lane + 64) * 52 + c] = e2 * inv;
        s.w[(lane + 96) * 52 + c] = e3 * inv;
    }
    if (tid < 128) s.w[tid * 52 + 51] = 0.0f;
    __syncthreads();

    // ---- aggr: out[p][c] = sum_k w[k][p] * sel[k][c], f32x2 over p ----
    {
        ull acc2[26];
        #pragma unroll
        for (int p = 0; p < 26; p++) acc2[p] = 0ull;
        const int c = tid;
        float xv = xb[(size_t)s.selidx[0] * DIMV + c];
        #pragma unroll 2
        for (int k = 0; k < 128; k++) {
            const float nxt = (k < 127) ? xb[(size_t)s.selidx[k + 1] * DIMV + c] : 0.0f;
            const ull x2 = pack2(xv, xv);
            const ull* wrow = reinterpret_cast<const ull*>(s.w + k * 52);
            #pragma unroll
            for (int p = 0; p < 26; p++) acc2[p] = ffma2(x2, wrow[p], acc2[p]);
            xv = nxt;
        }
        #pragma unroll
        for (int p = 0; p < 26; p++) {
            float2 v = unpack2(acc2[p]);
            ob[(2 * p) * DIMV + c] = v.x;
            if (2 * p + 1 < KP) ob[(2 * p + 1) * DIMV + c] = v.y;
        }
    }
}

extern "C" void kernel_launch(void* const* d_in, const int* in_sizes, int n_in,
                              void* d_out, int out_size) {
    (void)in_sizes; (void)n_in; (void)out_size;
    const float* x    = (const float*)d_in[0];
    const float* ca   = (const float*)d_in[1];
    const float* lng  = (const float*)d_in[2];
    const float* lnb  = (const float*)d_in[3];
    const float* W1   = (const float*)d_in[4];
    const float* b1   = (const float*)d_in[5];
    const float* W2   = (const float*)d_in[6];
    const float* b2   = (const float*)d_in[7];
    const float* sc   = (const float*)d_in[8];
    float* out = (float*)d_out;

    static_assert(sizeof(Smem) <= 227 * 1024, "smem too big");
    cudaFuncSetAttribute(ATRM_73581379715509_kernel,
                         cudaFuncAttributeMaxDynamicSharedMemorySize,
                         (int)sizeof(Smem));
    ATRM_73581379715509_kernel<<<512, 512, sizeof(Smem)>>>(
        x, ca, lng, lnb, W1, b1, W2, b2, sc, out);
}